// round 1
// baseline (speedup 1.0000x reference)
#include <cuda_runtime.h>
#include <cuda_bf16.h>
#include <cstdint>

// Problem constants
#define Bb 8
#define LL 1024
#define HH 8
#define EE 64
#define DD 64
#define SCALE 0.125f   // 1/sqrt(64)

// Output layout (concatenated flattened tuple):
//   V:      (B,L,H,D)   at 0              size 4,194,304
//   series: (B,H,L,S)   at 4,194,304      size 67,108,864
//   prior:  (B,L,S)     at 71,303,168     size 8,388,608
#define OFF_SERIES 4194304
#define OFF_PRIOR  71303168

// Scratch: per-(b,h,row,ntile) partial row sums of unnormalized exp scores.
__device__ float g_partial[Bb * HH * LL * 8];  // 2 MB

// ---------------------------------------------------------------------------
// Kernel 1: E = exp(scale * Q K^T) for causal (lower-triangular) tiles.
// grid = (nt=8, mt=8, bh=64), block = 256 threads, tile 128x128, micro 8x8.
// Upper tiles (nt>mt): zero-fill fast path.
// Also emits partial row sums to g_partial (no atomics).
// ---------------------------------------------------------------------------
__global__ __launch_bounds__(256, 2)
void k_scores(const float* __restrict__ Q, const float* __restrict__ K,
              float* __restrict__ series) {
    const int nt = blockIdx.x;
    const int mt = blockIdx.y;
    const int bh = blockIdx.z;          // b*8 + h
    const int b  = bh >> 3;
    const int h  = bh & 7;
    const int tid = threadIdx.x;
    const int tx = tid & 15;            // column group (8 cols)
    const int ty = tid >> 4;            // row group (8 rows)

    float* S = series + (size_t)bh * LL * LL;
    const int row0 = mt * 128, col0 = nt * 128;

    if (nt > mt) {
        // strictly-upper tile: write zeros (softmax of -inf)
        const float4 z = make_float4(0.f, 0.f, 0.f, 0.f);
        #pragma unroll
        for (int i = 0; i < 16; i++) {
            int flat = i * 256 + tid;          // 4096 float4 = 128 rows x 32
            int r = flat >> 5;
            int c = (flat & 31) << 2;
            *(float4*)(S + (size_t)(row0 + r) * LL + col0 + c) = z;
        }
        return;
    }

    __shared__ __align__(16) float Qs[32][132];
    __shared__ __align__(16) float Ks[32][132];

    float acc[8][8];
    #pragma unroll
    for (int u = 0; u < 8; u++)
        #pragma unroll
        for (int v = 0; v < 8; v++) acc[u][v] = 0.f;

    const float* Qg = Q + (size_t)b * LL * (HH * EE) + h * EE;  // + l*512 + e
    const float* Kg = K + (size_t)b * LL * (HH * EE) + h * EE;

    for (int kk = 0; kk < EE; kk += 32) {
        // cooperative transposed loads: Qs[k][m], Ks[k][n]
        #pragma unroll
        for (int it = 0; it < 4; it++) {
            int flat = it * 256 + tid;     // 1024 float4 loads
            int m  = flat & 127;
            int kc = flat >> 7;            // 0..7 (4-wide k chunk)
            float4 v = *(const float4*)(Qg + (size_t)(row0 + m) * 512 + kk + kc * 4);
            Qs[kc * 4 + 0][m] = v.x; Qs[kc * 4 + 1][m] = v.y;
            Qs[kc * 4 + 2][m] = v.z; Qs[kc * 4 + 3][m] = v.w;
            float4 w = *(const float4*)(Kg + (size_t)(col0 + m) * 512 + kk + kc * 4);
            Ks[kc * 4 + 0][m] = w.x; Ks[kc * 4 + 1][m] = w.y;
            Ks[kc * 4 + 2][m] = w.z; Ks[kc * 4 + 3][m] = w.w;
        }
        __syncthreads();

        #pragma unroll 4
        for (int k = 0; k < 32; k++) {
            float a[8], bb[8];
            *(float4*)(&a[0])  = *(const float4*)(&Qs[k][ty * 8]);
            *(float4*)(&a[4])  = *(const float4*)(&Qs[k][ty * 8 + 4]);
            *(float4*)(&bb[0]) = *(const float4*)(&Ks[k][tx * 8]);
            *(float4*)(&bb[4]) = *(const float4*)(&Ks[k][tx * 8 + 4]);
            #pragma unroll
            for (int u = 0; u < 8; u++)
                #pragma unroll
                for (int v = 0; v < 8; v++)
                    acc[u][v] = fmaf(a[u], bb[v], acc[u][v]);
        }
        __syncthreads();
    }

    // mask + exp + write + partial row sums
    const int lane = tid & 31;
    #pragma unroll
    for (int u = 0; u < 8; u++) {
        const int row = row0 + ty * 8 + u;
        float rsum = 0.f;
        #pragma unroll
        for (int v = 0; v < 8; v++) {
            const int col = col0 + tx * 8 + v;
            float e = (col <= row) ? __expf(SCALE * acc[u][v]) : 0.f;
            acc[u][v] = e;
            rsum += e;
        }
        // reduce across the 16 tx lanes (lanes 0-15 / 16-31 share ty)
        #pragma unroll
        for (int off = 1; off < 16; off <<= 1)
            rsum += __shfl_xor_sync(0xffffffffu, rsum, off);
        if ((lane & 15) == 0)
            g_partial[((size_t)bh * LL + row) * 8 + nt] = rsum;

        float* dst = S + (size_t)row * LL + col0 + tx * 8;
        *(float4*)dst       = make_float4(acc[u][0], acc[u][1], acc[u][2], acc[u][3]);
        *(float4*)(dst + 4) = make_float4(acc[u][4], acc[u][5], acc[u][6], acc[u][7]);
    }
}

// ---------------------------------------------------------------------------
// Kernel 2: normalize series in-place (P = E / rowsum) and O = P @ V.
// grid = (mt=8, bh=64), block 256, O tile 128x64, micro 8x4.
// ---------------------------------------------------------------------------
__global__ __launch_bounds__(256, 2)
void k_av(const float* __restrict__ V, float* __restrict__ series,
          float* __restrict__ outV) {
    const int mt = blockIdx.x;
    const int bh = blockIdx.y;
    const int b  = bh >> 3;
    const int h  = bh & 7;
    const int tid = threadIdx.x;
    const int tx = tid & 15;     // d group (4 cols)
    const int ty = tid >> 4;     // m group (8 rows)
    const int row0 = mt * 128;

    __shared__ float rinv[128];
    __shared__ __align__(16) float Ps[32][132];  // [s][m]
    __shared__ __align__(16) float Vs[32][68];   // [s][d]

    if (tid < 128) {
        float s = 0.f;
        for (int nt = 0; nt <= mt; nt++)
            s += g_partial[((size_t)bh * LL + row0 + tid) * 8 + nt];
        rinv[tid] = 1.0f / s;
    }
    __syncthreads();

    float acc[8][4];
    #pragma unroll
    for (int u = 0; u < 8; u++)
        #pragma unroll
        for (int v = 0; v < 4; v++) acc[u][v] = 0.f;

    float* S = series + (size_t)bh * LL * LL;
    const float* Vg = V + (size_t)b * LL * (HH * DD) + h * DD;

    for (int nt = 0; nt <= mt; nt++) {
        for (int sc = 0; sc < 128; sc += 32) {
            const int s0 = nt * 128 + sc;
            // load E chunk, normalize, write back P, stage transposed in smem
            #pragma unroll
            for (int it = 0; it < 4; it++) {
                int flat = it * 256 + tid;   // 1024 float4
                int m  = flat & 127;
                int c4 = flat >> 7;          // 0..7
                float* g = S + (size_t)(row0 + m) * LL + s0 + c4 * 4;
                float4 v = *(float4*)g;
                float r = rinv[m];
                v.x *= r; v.y *= r; v.z *= r; v.w *= r;
                *(float4*)g = v;
                Ps[c4 * 4 + 0][m] = v.x; Ps[c4 * 4 + 1][m] = v.y;
                Ps[c4 * 4 + 2][m] = v.z; Ps[c4 * 4 + 3][m] = v.w;
            }
            // load V chunk [32 s][64 d]
            #pragma unroll
            for (int it = 0; it < 2; it++) {
                int flat = it * 256 + tid;   // 512 float4
                int sr = flat >> 4;
                int d4 = (flat & 15) << 2;
                *(float4*)&Vs[sr][d4] =
                    *(const float4*)(Vg + (size_t)(s0 + sr) * 512 + d4);
            }
            __syncthreads();

            #pragma unroll 4
            for (int k = 0; k < 32; k++) {
                float a[8], bb[4];
                *(float4*)(&a[0]) = *(const float4*)(&Ps[k][ty * 8]);
                *(float4*)(&a[4]) = *(const float4*)(&Ps[k][ty * 8 + 4]);
                *(float4*)(&bb[0]) = *(const float4*)(&Vs[k][tx * 4]);
                #pragma unroll
                for (int u = 0; u < 8; u++)
                    #pragma unroll
                    for (int v = 0; v < 4; v++)
                        acc[u][v] = fmaf(a[u], bb[v], acc[u][v]);
            }
            __syncthreads();
        }
    }

    float* Og = outV + (size_t)b * LL * (HH * DD) + h * DD;
    #pragma unroll
    for (int u = 0; u < 8; u++) {
        const int row = row0 + ty * 8 + u;
        *(float4*)(Og + (size_t)row * 512 + tx * 4) =
            make_float4(acc[u][0], acc[u][1], acc[u][2], acc[u][3]);
    }
}

// ---------------------------------------------------------------------------
// Kernel 3: prior association.
// prior[b,i,s] = sum_h exp(-|i-s| / sigma[b,h,s]), row-normalized over s
// (the 1/H mean factor cancels in the normalization).
// grid = (32 row-tiles, B), block 256; each block handles 32 rows i,
// staging -1/sigma for all (h,s) once in smem.
// ---------------------------------------------------------------------------
__global__ __launch_bounds__(256)
void k_prior(const float* __restrict__ sigma, float* __restrict__ prior) {
    const int b  = blockIdx.y;
    const int i0 = blockIdx.x * 32;
    const int tid = threadIdx.x;

    __shared__ float rl[8][1024];    // -1/sigma[b,h,s]
    __shared__ float red[8];

    for (int idx = tid; idx < 8 * 1024; idx += 256) {
        int h = idx >> 10;
        int s = idx & 1023;
        rl[h][s] = -1.0f / sigma[((size_t)b * 8 + h) * 1024 + s];
    }
    __syncthreads();

    const int lane = tid & 31, wid = tid >> 5;

    for (int ii = 0; ii < 32; ii++) {
        const int i = i0 + ii;
        float p[4];
        float sum = 0.f;
        #pragma unroll
        for (int j = 0; j < 4; j++) {
            const int s = tid + j * 256;
            const float d = (float)((i > s) ? (i - s) : (s - i));
            float a = 0.f;
            #pragma unroll
            for (int h = 0; h < 8; h++)
                a += __expf(d * rl[h][s]);
            p[j] = a;
            sum += a;
        }
        #pragma unroll
        for (int off = 16; off; off >>= 1)
            sum += __shfl_xor_sync(0xffffffffu, sum, off);
        if (lane == 0) red[wid] = sum;
        __syncthreads();
        float tot = 0.f;
        #pragma unroll
        for (int w = 0; w < 8; w++) tot += red[w];
        const float inv = 1.0f / tot;
        float* dst = prior + (size_t)(b * 1024 + i) * 1024;
        #pragma unroll
        for (int j = 0; j < 4; j++)
            dst[tid + j * 256] = p[j] * inv;
        __syncthreads();
    }
}

// ---------------------------------------------------------------------------
extern "C" void kernel_launch(void* const* d_in, const int* in_sizes, int n_in,
                              void* d_out, int out_size) {
    (void)in_sizes; (void)n_in; (void)out_size;
    const float* Q   = (const float*)d_in[0];
    const float* K   = (const float*)d_in[1];
    const float* V   = (const float*)d_in[2];
    const float* sig = (const float*)d_in[3];
    float* out    = (float*)d_out;
    float* outV   = out;                 // (B,L,H,D)
    float* series = out + OFF_SERIES;    // (B,H,L,S)
    float* prior  = out + OFF_PRIOR;     // (B,L,S)

    k_scores<<<dim3(8, 8, Bb * HH), 256>>>(Q, K, series);
    k_av    <<<dim3(8, Bb * HH),   256>>>(V, series, outV);
    k_prior <<<dim3(32, Bb),       256>>>(sig, prior);
}

// round 2
// speedup vs baseline: 3.4912x; 3.4912x over previous
#include <cuda_runtime.h>
#include <cuda_bf16.h>
#include <cstdint>

// Problem constants
#define Bb 8
#define LL 1024
#define HH 8
#define EE 64
#define DD 64
#define SCALE 0.125f   // 1/sqrt(64)

// Output layout (concatenated flattened tuple):
//   V:      (B,L,H,D)   at 0              size 4,194,304
//   series: (B,H,L,S)   at 4,194,304      size 67,108,864
//   prior:  (B,L,S)     at 71,303,168     size 8,388,608
#define OFF_SERIES 4194304
#define OFF_PRIOR  71303168

// Scratch: per-(b,h,row,ntile) partial row sums of unnormalized exp scores.
__device__ float g_partial[Bb * HH * LL * 8];  // 2 MB

// ---------------------------------------------------------------------------
// Kernel 1: E = exp(scale * Q K^T) for causal (lower-triangular) tiles.
// grid = (nt=8, mt=8, bh=64), block = 256 threads, tile 128x128, micro 8x8.
// Upper tiles (nt>mt): zero-fill fast path.
// Global loads: lanes traverse the contiguous e-axis (4 lines per LDG.128).
// ---------------------------------------------------------------------------
__global__ __launch_bounds__(256, 2)
void k_scores(const float* __restrict__ Q, const float* __restrict__ K,
              float* __restrict__ series) {
    const int nt = blockIdx.x;
    const int mt = blockIdx.y;
    const int bh = blockIdx.z;          // b*8 + h
    const int b  = bh >> 3;
    const int h  = bh & 7;
    const int tid = threadIdx.x;
    const int tx = tid & 15;            // column group (8 cols)
    const int ty = tid >> 4;            // row group (8 rows)

    float* S = series + (size_t)bh * LL * LL;
    const int row0 = mt * 128, col0 = nt * 128;

    if (nt > mt) {
        // strictly-upper tile: write zeros (softmax of -inf)
        const float4 z = make_float4(0.f, 0.f, 0.f, 0.f);
        #pragma unroll
        for (int i = 0; i < 16; i++) {
            int flat = i * 256 + tid;          // 4096 float4 = 128 rows x 32
            int r = flat >> 5;
            int c = (flat & 31) << 2;
            *(float4*)(S + (size_t)(row0 + r) * LL + col0 + c) = z;
        }
        return;
    }

    __shared__ __align__(16) float Qs[32][132];
    __shared__ __align__(16) float Ks[32][132];

    float acc[8][8];
    #pragma unroll
    for (int u = 0; u < 8; u++)
        #pragma unroll
        for (int v = 0; v < 8; v++) acc[u][v] = 0.f;

    const float* Qg = Q + (size_t)b * LL * (HH * EE) + h * EE;  // + l*512 + e
    const float* Kg = K + (size_t)b * LL * (HH * EE) + h * EE;

    for (int kk = 0; kk < EE; kk += 32) {
        // cooperative transposed loads, lanes along contiguous e:
        //   c4 = flat&7 (8 float4 across the 32-wide k-chunk), m = flat>>3
        #pragma unroll
        for (int it = 0; it < 4; it++) {
            int flat = it * 256 + tid;     // 1024 float4 per matrix
            int c4 = flat & 7;
            int m  = flat >> 3;
            float4 v = *(const float4*)(Qg + (size_t)(row0 + m) * 512 + kk + c4 * 4);
            Qs[c4 * 4 + 0][m] = v.x; Qs[c4 * 4 + 1][m] = v.y;
            Qs[c4 * 4 + 2][m] = v.z; Qs[c4 * 4 + 3][m] = v.w;
            float4 w = *(const float4*)(Kg + (size_t)(col0 + m) * 512 + kk + c4 * 4);
            Ks[c4 * 4 + 0][m] = w.x; Ks[c4 * 4 + 1][m] = w.y;
            Ks[c4 * 4 + 2][m] = w.z; Ks[c4 * 4 + 3][m] = w.w;
        }
        __syncthreads();

        #pragma unroll 4
        for (int k = 0; k < 32; k++) {
            float a[8], bb[8];
            *(float4*)(&a[0])  = *(const float4*)(&Qs[k][ty * 8]);
            *(float4*)(&a[4])  = *(const float4*)(&Qs[k][ty * 8 + 4]);
            *(float4*)(&bb[0]) = *(const float4*)(&Ks[k][tx * 8]);
            *(float4*)(&bb[4]) = *(const float4*)(&Ks[k][tx * 8 + 4]);
            #pragma unroll
            for (int u = 0; u < 8; u++)
                #pragma unroll
                for (int v = 0; v < 8; v++)
                    acc[u][v] = fmaf(a[u], bb[v], acc[u][v]);
        }
        __syncthreads();
    }

    // mask + exp + write + partial row sums
    const int lane = tid & 31;
    #pragma unroll
    for (int u = 0; u < 8; u++) {
        const int row = row0 + ty * 8 + u;
        float rsum = 0.f;
        #pragma unroll
        for (int v = 0; v < 8; v++) {
            const int col = col0 + tx * 8 + v;
            float e = (col <= row) ? __expf(SCALE * acc[u][v]) : 0.f;
            acc[u][v] = e;
            rsum += e;
        }
        // reduce across the 16 tx lanes (lanes 0-15 / 16-31 share ty)
        #pragma unroll
        for (int off = 1; off < 16; off <<= 1)
            rsum += __shfl_xor_sync(0xffffffffu, rsum, off);
        if ((lane & 15) == 0)
            g_partial[((size_t)bh * LL + row) * 8 + nt] = rsum;

        float* dst = S + (size_t)row * LL + col0 + tx * 8;
        *(float4*)dst       = make_float4(acc[u][0], acc[u][1], acc[u][2], acc[u][3]);
        *(float4*)(dst + 4) = make_float4(acc[u][4], acc[u][5], acc[u][6], acc[u][7]);
    }
}

// ---------------------------------------------------------------------------
// Kernel 2: normalize series in-place (P = E / rowsum) and O = P @ V.
// grid = (mt=8, bh=64), block 256, O tile 128x64, micro 8x4.
// Series RMW now coalesced: lanes traverse the contiguous s-axis.
// ---------------------------------------------------------------------------
__global__ __launch_bounds__(256, 2)
void k_av(const float* __restrict__ V, float* __restrict__ series,
          float* __restrict__ outV) {
    const int mt = blockIdx.x;
    const int bh = blockIdx.y;
    const int b  = bh >> 3;
    const int h  = bh & 7;
    const int tid = threadIdx.x;
    const int tx = tid & 15;     // d group (4 cols)
    const int ty = tid >> 4;     // m group (8 rows)
    const int row0 = mt * 128;

    __shared__ float rinv[128];
    __shared__ __align__(16) float Ps[32][132];  // [s][m]
    __shared__ __align__(16) float Vs[32][68];   // [s][d]

    if (tid < 128) {
        float s = 0.f;
        for (int nt = 0; nt <= mt; nt++)
            s += g_partial[((size_t)bh * LL + row0 + tid) * 8 + nt];
        rinv[tid] = 1.0f / s;
    }
    __syncthreads();

    float acc[8][4];
    #pragma unroll
    for (int u = 0; u < 8; u++)
        #pragma unroll
        for (int v = 0; v < 4; v++) acc[u][v] = 0.f;

    float* S = series + (size_t)bh * LL * LL;
    const float* Vg = V + (size_t)b * LL * (HH * DD) + h * DD;

    for (int nt = 0; nt <= mt; nt++) {
        for (int sc = 0; sc < 128; sc += 32) {
            const int s0 = nt * 128 + sc;
            // load E chunk (coalesced: lanes along s), normalize, write back P,
            // stage transposed in smem
            #pragma unroll
            for (int it = 0; it < 4; it++) {
                int flat = it * 256 + tid;   // 1024 float4
                int c4 = flat & 7;
                int m  = flat >> 3;
                float* g = S + (size_t)(row0 + m) * LL + s0 + c4 * 4;
                float4 v = *(float4*)g;
                float r = rinv[m];
                v.x *= r; v.y *= r; v.z *= r; v.w *= r;
                *(float4*)g = v;
                Ps[c4 * 4 + 0][m] = v.x; Ps[c4 * 4 + 1][m] = v.y;
                Ps[c4 * 4 + 2][m] = v.z; Ps[c4 * 4 + 3][m] = v.w;
            }
            // load V chunk [32 s][64 d] (already coalesced)
            #pragma unroll
            for (int it = 0; it < 2; it++) {
                int flat = it * 256 + tid;   // 512 float4
                int sr = flat >> 4;
                int d4 = (flat & 15) << 2;
                *(float4*)&Vs[sr][d4] =
                    *(const float4*)(Vg + (size_t)(s0 + sr) * 512 + d4);
            }
            __syncthreads();

            #pragma unroll 4
            for (int k = 0; k < 32; k++) {
                float a[8], bb[4];
                *(float4*)(&a[0]) = *(const float4*)(&Ps[k][ty * 8]);
                *(float4*)(&a[4]) = *(const float4*)(&Ps[k][ty * 8 + 4]);
                *(float4*)(&bb[0]) = *(const float4*)(&Vs[k][tx * 4]);
                #pragma unroll
                for (int u = 0; u < 8; u++)
                    #pragma unroll
                    for (int v = 0; v < 4; v++)
                        acc[u][v] = fmaf(a[u], bb[v], acc[u][v]);
            }
            __syncthreads();
        }
    }

    float* Og = outV + (size_t)b * LL * (HH * DD) + h * DD;
    #pragma unroll
    for (int u = 0; u < 8; u++) {
        const int row = row0 + ty * 8 + u;
        *(float4*)(Og + (size_t)row * 512 + tx * 4) =
            make_float4(acc[u][0], acc[u][1], acc[u][2], acc[u][3]);
    }
}

// ---------------------------------------------------------------------------
// Kernel 3: prior association (unchanged; not a bottleneck).
// ---------------------------------------------------------------------------
__global__ __launch_bounds__(256)
void k_prior(const float* __restrict__ sigma, float* __restrict__ prior) {
    const int b  = blockIdx.y;
    const int i0 = blockIdx.x * 32;
    const int tid = threadIdx.x;

    __shared__ float rl[8][1024];    // -1/sigma[b,h,s]
    __shared__ float red[8];

    for (int idx = tid; idx < 8 * 1024; idx += 256) {
        int h = idx >> 10;
        int s = idx & 1023;
        rl[h][s] = -1.0f / sigma[((size_t)b * 8 + h) * 1024 + s];
    }
    __syncthreads();

    const int lane = tid & 31, wid = tid >> 5;

    for (int ii = 0; ii < 32; ii++) {
        const int i = i0 + ii;
        float p[4];
        float sum = 0.f;
        #pragma unroll
        for (int j = 0; j < 4; j++) {
            const int s = tid + j * 256;
            const float d = (float)((i > s) ? (i - s) : (s - i));
            float a = 0.f;
            #pragma unroll
            for (int h = 0; h < 8; h++)
                a += __expf(d * rl[h][s]);
            p[j] = a;
            sum += a;
        }
        #pragma unroll
        for (int off = 16; off; off >>= 1)
            sum += __shfl_xor_sync(0xffffffffu, sum, off);
        if (lane == 0) red[wid] = sum;
        __syncthreads();
        float tot = 0.f;
        #pragma unroll
        for (int w = 0; w < 8; w++) tot += red[w];
        const float inv = 1.0f / tot;
        float* dst = prior + (size_t)(b * 1024 + i) * 1024;
        #pragma unroll
        for (int j = 0; j < 4; j++)
            dst[tid + j * 256] = p[j] * inv;
        __syncthreads();
    }
}

// ---------------------------------------------------------------------------
extern "C" void kernel_launch(void* const* d_in, const int* in_sizes, int n_in,
                              void* d_out, int out_size) {
    (void)in_sizes; (void)n_in; (void)out_size;
    const float* Q   = (const float*)d_in[0];
    const float* K   = (const float*)d_in[1];
    const float* V   = (const float*)d_in[2];
    const float* sig = (const float*)d_in[3];
    float* out    = (float*)d_out;
    float* outV   = out;                 // (B,L,H,D)
    float* series = out + OFF_SERIES;    // (B,H,L,S)
    float* prior  = out + OFF_PRIOR;     // (B,L,S)

    k_scores<<<dim3(8, 8, Bb * HH), 256>>>(Q, K, series);
    k_av    <<<dim3(8, Bb * HH),   256>>>(V, series, outV);
    k_prior <<<dim3(32, Bb),       256>>>(sig, prior);
}

// round 3
// speedup vs baseline: 3.5746x; 1.0239x over previous
#include <cuda_runtime.h>
#include <cuda_bf16.h>
#include <cstdint>

// Problem constants
#define Bb 8
#define LL 1024
#define HH 8
#define EE 64
#define DD 64
#define SCALE 0.125f   // 1/sqrt(64)

// Output layout (concatenated flattened tuple):
//   V:      (B,L,H,D)   at 0              size 4,194,304
//   series: (B,H,L,S)   at 4,194,304      size 67,108,864
//   prior:  (B,L,S)     at 71,303,168     size 8,388,608
#define OFF_SERIES 4194304
#define OFF_PRIOR  71303168

// Scratch: per-(b,h,row,ntile) partial row sums of unnormalized exp scores.
__device__ float g_partial[Bb * HH * LL * 8];  // 2 MB

// ---------------------------------------------------------------------------
// Kernel 1: E = exp(scale * Q K^T) for causal (lower-triangular) tiles.
// grid = (nt=8, mt=8, bh=64), block = 256, tile 128x128, micro 8x8 with
// stride-64 split fragments (conflict-free LDS) and xor-swizzled smem
// staging (conflict-free STS).
// ---------------------------------------------------------------------------
__global__ __launch_bounds__(256, 2)
void k_scores(const float* __restrict__ Q, const float* __restrict__ K,
              float* __restrict__ series) {
    const int nt = blockIdx.x;
    const int mt = blockIdx.y;
    const int bh = blockIdx.z;          // b*8 + h
    const int b  = bh >> 3;
    const int h  = bh & 7;
    const int tid = threadIdx.x;
    const int tx = tid & 15;
    const int ty = tid >> 4;

    float* S = series + (size_t)bh * LL * LL;
    const int row0 = mt * 128, col0 = nt * 128;

    if (nt > mt) {
        const float4 z = make_float4(0.f, 0.f, 0.f, 0.f);
        #pragma unroll
        for (int i = 0; i < 16; i++) {
            int flat = i * 256 + tid;
            int r = flat >> 5;
            int c = (flat & 31) << 2;
            *(float4*)(S + (size_t)(row0 + r) * LL + col0 + c) = z;
        }
        return;
    }

    __shared__ __align__(16) float Qs[32][132];
    __shared__ __align__(16) float Ks[32][132];

    float acc[8][8];
    #pragma unroll
    for (int u = 0; u < 8; u++)
        #pragma unroll
        for (int v = 0; v < 8; v++) acc[u][v] = 0.f;

    const float* Qg = Q + (size_t)b * LL * (HH * EE) + h * EE;  // + l*512 + e
    const float* Kg = K + (size_t)b * LL * (HH * EE) + h * EE;

    for (int kk = 0; kk < EE; kk += 32) {
        // cooperative transposed loads, lanes along contiguous e-axis;
        // stored column swizzled: mc = m ^ (4*c4)  (c4 = krow>>2)
        #pragma unroll
        for (int it = 0; it < 4; it++) {
            int flat = it * 256 + tid;     // 1024 float4 per matrix
            int c4 = flat & 7;
            int m  = flat >> 3;
            int mc = m ^ (c4 * 4);
            float4 v = *(const float4*)(Qg + (size_t)(row0 + m) * 512 + kk + c4 * 4);
            Qs[c4 * 4 + 0][mc] = v.x; Qs[c4 * 4 + 1][mc] = v.y;
            Qs[c4 * 4 + 2][mc] = v.z; Qs[c4 * 4 + 3][mc] = v.w;
            float4 w = *(const float4*)(Kg + (size_t)(col0 + m) * 512 + kk + c4 * 4);
            Ks[c4 * 4 + 0][mc] = w.x; Ks[c4 * 4 + 1][mc] = w.y;
            Ks[c4 * 4 + 2][mc] = w.z; Ks[c4 * 4 + 3][mc] = w.w;
        }
        __syncthreads();

        #pragma unroll 4
        for (int k = 0; k < 32; k++) {
            const int s4 = k & 28;                 // 4*(k>>2)
            const int ab = (ty * 4) ^ s4;          // a base col (row index m)
            const int bb0 = (tx * 4) ^ s4;         // b base
            float a[8], bv[8];
            *(float4*)(&a[0])  = *(const float4*)(&Qs[k][ab]);
            *(float4*)(&a[4])  = *(const float4*)(&Qs[k][ab + 64]);
            *(float4*)(&bv[0]) = *(const float4*)(&Ks[k][bb0]);
            *(float4*)(&bv[4]) = *(const float4*)(&Ks[k][bb0 + 64]);
            #pragma unroll
            for (int u = 0; u < 8; u++)
                #pragma unroll
                for (int v = 0; v < 8; v++)
                    acc[u][v] = fmaf(a[u], bv[v], acc[u][v]);
        }
        __syncthreads();
    }

    // mask + exp + write + tile-row sums
    // rows: u<4 -> ty*4+u ; u>=4 -> 64+ty*4+(u-4)
    // cols: v<4 -> tx*4+v ; v>=4 -> 64+tx*4+(v-4)
    const int lane = tid & 31;
    #pragma unroll
    for (int u = 0; u < 8; u++) {
        const int row = row0 + ty * 4 + ((u < 4) ? u : 64 + (u - 4));
        float rsum = 0.f;
        #pragma unroll
        for (int v = 0; v < 8; v++) {
            const int col = col0 + tx * 4 + ((v < 4) ? v : 64 + (v - 4));
            float e = (col <= row) ? __expf(SCALE * acc[u][v]) : 0.f;
            acc[u][v] = e;
            rsum += e;
        }
        // threads sharing this row = the 16 tx lanes of this half-warp
        #pragma unroll
        for (int off = 1; off < 16; off <<= 1)
            rsum += __shfl_xor_sync(0xffffffffu, rsum, off);
        if ((lane & 15) == 0)
            g_partial[((size_t)bh * LL + row) * 8 + nt] = rsum;

        float* dst = S + (size_t)row * LL + col0 + tx * 4;
        *(float4*)dst        = make_float4(acc[u][0], acc[u][1], acc[u][2], acc[u][3]);
        *(float4*)(dst + 64) = make_float4(acc[u][4], acc[u][5], acc[u][6], acc[u][7]);
    }
}

// ---------------------------------------------------------------------------
// Kernel 2: normalize series in-place (P = E / rowsum) and O = P @ V.
// grid = (mt=8, bh=64), block 256, O tile 128x64, micro 8x4.
// Ps staging now xor-swizzled (conflict-free STS); nt descends for L2 reuse.
// ---------------------------------------------------------------------------
__global__ __launch_bounds__(256, 2)
void k_av(const float* __restrict__ V, float* __restrict__ series,
          float* __restrict__ outV) {
    const int mt = blockIdx.x;
    const int bh = blockIdx.y;
    const int b  = bh >> 3;
    const int h  = bh & 7;
    const int tid = threadIdx.x;
    const int tx = tid & 15;     // d group (4 cols)
    const int ty = tid >> 4;     // m group (8 rows)
    const int row0 = mt * 128;

    __shared__ float rinv[128];
    __shared__ __align__(16) float Ps[32][132];  // [s][m], swizzled cols
    __shared__ __align__(16) float Vs[32][68];   // [s][d]

    if (tid < 128) {
        float s = 0.f;
        for (int nt = 0; nt <= mt; nt++)
            s += g_partial[((size_t)bh * LL + row0 + tid) * 8 + nt];
        rinv[tid] = 1.0f / s;
    }
    __syncthreads();

    float acc[8][4];
    #pragma unroll
    for (int u = 0; u < 8; u++)
        #pragma unroll
        for (int v = 0; v < 4; v++) acc[u][v] = 0.f;

    float* S = series + (size_t)bh * LL * LL;
    const float* Vg = V + (size_t)b * LL * (HH * DD) + h * DD;

    for (int nt = mt; nt >= 0; nt--) {
        for (int sc = 0; sc < 128; sc += 32) {
            const int s0 = nt * 128 + sc;
            // load E chunk (coalesced), normalize, write back P,
            // stage transposed+swizzled in smem
            #pragma unroll
            for (int it = 0; it < 4; it++) {
                int flat = it * 256 + tid;   // 1024 float4
                int c4 = flat & 7;
                int m  = flat >> 3;
                int mc = m ^ (c4 * 4);
                float* g = S + (size_t)(row0 + m) * LL + s0 + c4 * 4;
                float4 v = *(float4*)g;
                float r = rinv[m];
                v.x *= r; v.y *= r; v.z *= r; v.w *= r;
                *(float4*)g = v;
                Ps[c4 * 4 + 0][mc] = v.x; Ps[c4 * 4 + 1][mc] = v.y;
                Ps[c4 * 4 + 2][mc] = v.z; Ps[c4 * 4 + 3][mc] = v.w;
            }
            // load V chunk [32 s][64 d]
            #pragma unroll
            for (int it = 0; it < 2; it++) {
                int flat = it * 256 + tid;   // 512 float4
                int sr = flat >> 4;
                int d4 = (flat & 15) << 2;
                *(float4*)&Vs[sr][d4] =
                    *(const float4*)(Vg + (size_t)(s0 + sr) * 512 + d4);
            }
            __syncthreads();

            #pragma unroll 4
            for (int k = 0; k < 32; k++) {
                const int s4 = k & 28;
                const int i0 = (ty * 8) ^ s4;
                const int i1 = (ty * 8 + 4) ^ s4;
                float a[8], bv[4];
                *(float4*)(&a[0]) = *(const float4*)(&Ps[k][i0]);
                *(float4*)(&a[4]) = *(const float4*)(&Ps[k][i1]);
                *(float4*)(&bv[0]) = *(const float4*)(&Vs[k][tx * 4]);
                #pragma unroll
                for (int u = 0; u < 8; u++)
                    #pragma unroll
                    for (int v = 0; v < 4; v++)
                        acc[u][v] = fmaf(a[u], bv[v], acc[u][v]);
            }
            __syncthreads();
        }
    }

    float* Og = outV + (size_t)b * LL * (HH * DD) + h * DD;
    #pragma unroll
    for (int u = 0; u < 8; u++) {
        const int row = row0 + ty * 8 + u;
        *(float4*)(Og + (size_t)row * 512 + tx * 4) =
            make_float4(acc[u][0], acc[u][1], acc[u][2], acc[u][3]);
    }
}

// ---------------------------------------------------------------------------
// Kernel 3: prior association (MUFU-bound, ~20us; unchanged).
// ---------------------------------------------------------------------------
__global__ __launch_bounds__(256)
void k_prior(const float* __restrict__ sigma, float* __restrict__ prior) {
    const int b  = blockIdx.y;
    const int i0 = blockIdx.x * 32;
    const int tid = threadIdx.x;

    __shared__ float rl[8][1024];    // -1/sigma[b,h,s]
    __shared__ float red[8];

    for (int idx = tid; idx < 8 * 1024; idx += 256) {
        int h = idx >> 10;
        int s = idx & 1023;
        rl[h][s] = -1.0f / sigma[((size_t)b * 8 + h) * 1024 + s];
    }
    __syncthreads();

    const int lane = tid & 31, wid = tid >> 5;

    for (int ii = 0; ii < 32; ii++) {
        const int i = i0 + ii;
        float p[4];
        float sum = 0.f;
        #pragma unroll
        for (int j = 0; j < 4; j++) {
            const int s = tid + j * 256;
            const float d = (float)((i > s) ? (i - s) : (s - i));
            float a = 0.f;
            #pragma unroll
            for (int h = 0; h < 8; h++)
                a += __expf(d * rl[h][s]);
            p[j] = a;
            sum += a;
        }
        #pragma unroll
        for (int off = 16; off; off >>= 1)
            sum += __shfl_xor_sync(0xffffffffu, sum, off);
        if (lane == 0) red[wid] = sum;
        __syncthreads();
        float tot = 0.f;
        #pragma unroll
        for (int w = 0; w < 8; w++) tot += red[w];
        const float inv = 1.0f / tot;
        float* dst = prior + (size_t)(b * 1024 + i) * 1024;
        #pragma unroll
        for (int j = 0; j < 4; j++)
            dst[tid + j * 256] = p[j] * inv;
        __syncthreads();
    }
}

// ---------------------------------------------------------------------------
extern "C" void kernel_launch(void* const* d_in, const int* in_sizes, int n_in,
                              void* d_out, int out_size) {
    (void)in_sizes; (void)n_in; (void)out_size;
    const float* Q   = (const float*)d_in[0];
    const float* K   = (const float*)d_in[1];
    const float* V   = (const float*)d_in[2];
    const float* sig = (const float*)d_in[3];
    float* out    = (float*)d_out;
    float* outV   = out;                 // (B,L,H,D)
    float* series = out + OFF_SERIES;    // (B,H,L,S)
    float* prior  = out + OFF_PRIOR;     // (B,L,S)

    k_scores<<<dim3(8, 8, Bb * HH), 256>>>(Q, K, series);
    k_av    <<<dim3(8, Bb * HH),   256>>>(V, series, outV);
    k_prior <<<dim3(32, Bb),       256>>>(sig, prior);
}